// round 10
// baseline (speedup 1.0000x reference)
#include <cuda_runtime.h>
#include <cstdint>

// FeaturesLoss: mma.sync m16n8k8 tf32, persistent CTAs, double-buffered K=64
// chunks, LDS.64 fragment loads from a k-permuted feature copy, 128x256 tiles
// (64x64/warp), ordered-pair (j>i, x2) coverage, deterministic reduction.

#define BN    8192
#define DIM   128
#define TM    128
#define TNJ   256
#define NBLK2 1056                  // sum over bi of (32 - bi/2)
#define MARGIN 2.0f
#define NPERS 152

#define PITCH  288                  // bytes per row per chunk (72 uint32)
#define PITCHW 72                   // pitch in uint32
#define ACH    (TM  * PITCH)        // 36864
#define BCH    (TNJ * PITCH)        // 73728
#define SLOT   (ACH + BCH)          // 110592
#define SM_STG (2 * SLOT)           // 221184
#define STGSZ  3072
#define SM_TOT (SM_STG + 2 * STGSZ) // 227328

__device__ float      g_sq[BN];
__device__ int        g_lab[BN];
__device__ float      g_perm[BN * DIM];   // k-permuted fp32 features (4 MB)
__device__ float      g_partials[NBLK2];
__device__ long long  g_poscnt[NBLK2];
__device__ unsigned   g_ticket;

__device__ __forceinline__ uint32_t smem_u32(const void* p) {
    uint32_t a;
    asm("{ .reg .u64 t; cvta.to.shared.u64 t, %1; cvt.u32.u64 %0, t; }" : "=r"(a) : "l"(p));
    return a;
}
__device__ __forceinline__ void cp16(uint32_t dst, const void* src) {
    asm volatile("cp.async.cg.shared.global [%0], [%1], 16;" :: "r"(dst), "l"(src));
}
__device__ __forceinline__ void cp_commit() {
    asm volatile("cp.async.commit_group;" ::: "memory");
}
template<int N> __device__ __forceinline__ void cp_wait() {
    asm volatile("cp.async.wait_group %0;" :: "n"(N) : "memory");
}
__device__ __forceinline__ void lds64(uint32_t& lo, uint32_t& hi, uint32_t addr) {
    asm volatile("ld.shared.v2.b32 {%0,%1}, [%2];" : "=r"(lo), "=r"(hi) : "r"(addr));
}
__device__ __forceinline__ void mma_tf32(float c[4], uint32_t a0, uint32_t a1,
                                         uint32_t a2, uint32_t a3,
                                         uint32_t b0, uint32_t b1) {
    asm volatile(
        "mma.sync.aligned.m16n8k8.row.col.f32.tf32.tf32.f32 "
        "{%0,%1,%2,%3}, {%4,%5,%6,%7}, {%8,%9}, {%0,%1,%2,%3};"
        : "+f"(c[0]), "+f"(c[1]), "+f"(c[2]), "+f"(c[3])
        : "r"(a0), "r"(a1), "r"(a2), "r"(a3), "r"(b0), "r"(b1));
}
__device__ __forceinline__ void decode_tile(int idx, int& i0, int& j0) {
    int bi = 0;
    while (idx >= 32 - (bi >> 1)) { idx -= 32 - (bi >> 1); bi++; }
    i0 = bi * TM;
    j0 = ((bi >> 1) + idx) * TNJ;
}

// ---------------------------------------------------------------------------
// Kernel 0: norms, labels, and k-permuted feature copy.
// Group layout per 8 k-cols: [k0,k4,k1,k5,k2,k6,k3,k7] so that fragment pairs
// (k=tig, k=tig+4) are adjacent for LDS.64.
// ---------------------------------------------------------------------------
__global__ void prep_kernel(const float* __restrict__ F,
                            const void* __restrict__ labels_raw) {
    if (blockIdx.x == 0 && threadIdx.x == 0) g_ticket = 0;  // reset per replay

    int warp = (blockIdx.x * blockDim.x + threadIdx.x) >> 5;
    int lane = threadIdx.x & 31;
    if (warp >= BN) return;

    const int* w = (const int*)labels_raw;
    int probe = w[2 * lane + 1];
    unsigned is64 = __all_sync(0xffffffffu, probe == 0);

    const float4* row = (const float4*)(F + (size_t)warp * DIM);
    float4 f = row[lane];

    // permuted write: partner exchange within k8 group
    float px = __shfl_xor_sync(0xffffffffu, f.x, 1);
    float py = __shfl_xor_sync(0xffffffffu, f.y, 1);
    float pz = __shfl_xor_sync(0xffffffffu, f.z, 1);
    float pw = __shfl_xor_sync(0xffffffffu, f.w, 1);
    float4 o;
    if ((lane & 1) == 0) o = make_float4(f.x, px, f.y, py);
    else                 o = make_float4(pz, f.z, pw, f.w);
    *(float4*)(g_perm + (size_t)warp * DIM + lane * 4) = o;

    float s = f.x * f.x + f.y * f.y + f.z * f.z + f.w * f.w;
    #pragma unroll
    for (int off = 16; off; off >>= 1)
        s += __shfl_xor_sync(0xffffffffu, s, off);

    if (lane == 0) {
        g_sq[warp] = s;
        int lab;
        if (is64) lab = (int)((const long long*)labels_raw)[warp];
        else      lab = w[warp];
        g_lab[warp] = lab;
    }
}

// ---------------------------------------------------------------------------
// Issue one K=64 chunk (kc = 0/1) of tile (i0,j0) into buffer slot.
__device__ __forceinline__ void issue_chunk(uint32_t sbase, int i0, int j0,
                                            int kc, int slot, int t) {
    const char* P = (const char*)g_perm;          // 512 B per feature row
    uint32_t abase = sbase + slot * SLOT;
    uint32_t bbase = abase + ACH;
    #pragma unroll
    for (int s = t; s < TM * 16; s += 256) {      // A: 2048 16B segs
        int r = s >> 4, q = s & 15;
        cp16(abase + r * PITCH + q * 16,
             P + (size_t)(i0 + r) * 512 + kc * 256 + q * 16);
    }
    #pragma unroll
    for (int s = t; s < TNJ * 16; s += 256) {     // B: 4096 16B segs
        int r = s >> 4, q = s & 15;
        cp16(bbase + r * PITCH + q * 16,
             P + (size_t)(j0 + r) * 512 + kc * 256 + q * 16);
    }
}

// ---------------------------------------------------------------------------
__global__ void __launch_bounds__(256, 1)
tile_kernel() {
    extern __shared__ char smem[];
    uint32_t sbase = smem_u32(smem);

    int t = threadIdx.x;
    int wid = t >> 5, lane = t & 31;
    int gid = lane >> 2, tig = lane & 3;
    int wm = wid & 1, wn = wid >> 1;
    int mbase = wm * 64, nbase = wn * 64;

    __shared__ int s_tick;
    __shared__ float rbuf[8];
    __shared__ int   rcnt[8];

    if (t == 0) s_tick = (int)atomicAdd(&g_ticket, 1u);
    __syncthreads();
    int cur = s_tick;
    if (cur >= NBLK2) return;

    int i0, j0;
    decode_tile(cur, i0, j0);

    // prologue: fill both chunk slots for the first tile
    issue_chunk(sbase, i0, j0, 0, 0, t);
    cp_commit();
    issue_chunk(sbase, i0, j0, 1, 1, t);
    cp_commit();

    int parity = 0;
    for (;;) {
        if (t == 0) s_tick = (int)atomicAdd(&g_ticket, 1u);
        {
            char* stg = smem + SM_STG + parity * STGSZ;
            float* sqI = (float*)stg;
            float* sqJ = (float*)(stg + 512);
            int*   lbI = (int*)  (stg + 1536);
            int*   lbJ = (int*)  (stg + 2048);
            if (t < TM) { sqI[t] = g_sq[i0 + t]; lbI[t] = g_lab[i0 + t]; }
            sqJ[t] = g_sq[j0 + t];
            lbJ[t] = g_lab[j0 + t];
        }
        __syncthreads();
        int nxt = s_tick;
        int ni0 = 0, nj0 = 0;
        bool more = (nxt < NBLK2);
        if (more) decode_tile(nxt, ni0, nj0);

        float acc[4][8][4];
        #pragma unroll
        for (int mf = 0; mf < 4; mf++)
            #pragma unroll
            for (int nf = 0; nf < 8; nf++)
                #pragma unroll
                for (int rr = 0; rr < 4; rr++) acc[mf][nf][rr] = 0.0f;

        // two K=64 chunk slots; refill slot c with next tile's chunk c
        #pragma unroll
        for (int c = 0; c < 2; c++) {
            cp_wait<1>();
            __syncthreads();

            uint32_t abase = sbase + c * SLOT;
            uint32_t bbase = abase + ACH;
            uint32_t arow0 = abase + (mbase + gid)     * PITCH + tig * 8;
            uint32_t arow1 = abase + (mbase + gid + 8) * PITCH + tig * 8;
            uint32_t brow  = bbase + (nbase + gid)     * PITCH + tig * 8;

            #pragma unroll
            for (int kk = 0; kk < 8; kk++) {
                uint32_t ko = kk * 32;                 // 8 uint32 = 32 B per k8
                uint32_t a[4][4];
                #pragma unroll
                for (int mf = 0; mf < 4; mf++) {
                    lds64(a[mf][0], a[mf][2], arow0 + mf * (16 * PITCH) + ko);
                    lds64(a[mf][1], a[mf][3], arow1 + mf * (16 * PITCH) + ko);
                }
                uint32_t b[8][2];
                #pragma unroll
                for (int nf = 0; nf < 8; nf++)
                    lds64(b[nf][0], b[nf][1], brow + nf * (8 * PITCH) + ko);
                #pragma unroll
                for (int mf = 0; mf < 4; mf++)
                    #pragma unroll
                    for (int nf = 0; nf < 8; nf++)
                        mma_tf32(acc[mf][nf], a[mf][0], a[mf][1], a[mf][2], a[mf][3],
                                 b[nf][0], b[nf][1]);
            }

            __syncthreads();                // everyone done reading slot c
            if (more) issue_chunk(sbase, ni0, nj0, c, c, t);
            cp_commit();                    // possibly-empty group keeps FIFO order
        }

        // ---- fused epilogue: ordered pairs gj > gi, weight x2 ----
        const char* stg = smem + SM_STG + parity * STGSZ;
        const float* sqI = (const float*)stg;
        const float* sqJ = (const float*)(stg + 512);
        const int*   lbI = (const int*)  (stg + 1536);
        const int*   lbJ = (const int*)  (stg + 2048);

        float lsum = 0.0f;
        int   lcnt = 0;
        #pragma unroll
        for (int mf = 0; mf < 4; mf++) {
            #pragma unroll
            for (int rr = 0; rr < 2; rr++) {
                int m  = mbase + 16 * mf + gid + 8 * rr;
                int gi = i0 + m;
                float sqi = sqI[m];
                int   li  = lbI[m];
                #pragma unroll
                for (int nf = 0; nf < 8; nf++) {
                    #pragma unroll
                    for (int cc = 0; cc < 2; cc++) {
                        int n  = nbase + 8 * nf + tig * 2 + cc;
                        int gj = j0 + n;
                        if (gj <= gi) continue;
                        float dot = acc[mf][nf][rr * 2 + cc];
                        float d2 = fmaxf(sqi + sqJ[n] - 2.0f * dot, 0.0f);
                        if (li == lbJ[n]) {
                            lsum += d2;
                            lcnt++;
                        } else if (d2 < MARGIN * MARGIN) {   // ~never (8 sigma)
                            float h = MARGIN - sqrtf(d2);
                            lsum += h * h;
                        }
                    }
                }
            }
        }

        #pragma unroll
        for (int off = 16; off; off >>= 1) {
            lsum += __shfl_xor_sync(0xffffffffu, lsum, off);
            lcnt += __shfl_xor_sync(0xffffffffu, lcnt, off);
        }
        if (lane == 0) { rbuf[wid] = lsum; rcnt[wid] = lcnt; }
        __syncthreads();
        if (t == 0) {
            float s = 0.0f; long long c = 0;
            #pragma unroll
            for (int wd = 0; wd < 8; wd++) { s += rbuf[wd]; c += rcnt[wd]; }
            g_partials[cur] = s * 2.0f;
            g_poscnt[cur]   = c * 2LL;
        }

        if (!more) break;
        cur = nxt; i0 = ni0; j0 = nj0; parity ^= 1;
    }
}

// ---------------------------------------------------------------------------
__global__ void finalize_kernel(float* __restrict__ out) {
    int t = threadIdx.x;
    double s = 0.0; long long c = 0;
    for (int i = t; i < NBLK2; i += 256) {
        s += (double)g_partials[i];
        c += g_poscnt[i];
    }
    __shared__ double    sd[256];
    __shared__ long long sc[256];
    sd[t] = s; sc[t] = c;
    __syncthreads();
    for (int off = 128; off; off >>= 1) {
        if (t < off) { sd[t] += sd[t + off]; sc[t] += sc[t + off]; }
        __syncthreads();
    }
    if (t == 0) {
        double total = sd[0];
        double denom = (double)((long long)BN * (BN - 1));
        out[0] = (float)(sc[0] > 0 ? total / denom : total);
    }
}

// ---------------------------------------------------------------------------
extern "C" void kernel_launch(void* const* d_in, const int* in_sizes, int n_in,
                              void* d_out, int out_size) {
    const float* F      = (const float*)d_in[0];
    const void*  labels = d_in[1];
    float*       out    = (float*)d_out;

    cudaFuncSetAttribute(tile_kernel,
                         cudaFuncAttributeMaxDynamicSharedMemorySize, SM_TOT);

    prep_kernel<<<BN / 8, 256>>>(F, labels);
    tile_kernel<<<NPERS, 256, SM_TOT>>>();
    finalize_kernel<<<1, 256>>>(out);
}

// round 11
// speedup vs baseline: 1.3315x; 1.3315x over previous
#include <cuda_runtime.h>
#include <cuda_fp16.h>
#include <cstdint>

// FeaturesLoss: mma.sync m16n8k16 fp16 in the R9 persistent 4-chunk ring.
// 128x256 tiles (64x64/warp), ordered-pair (j>i, x2), deterministic reduction.

#define BN    8192
#define DIM   128
#define TM    128
#define TNJ   256
#define NBLK2 1056                  // sum over bi of (32 - bi/2)
#define MARGIN 2.0f
#define NPERS 152

#define NCHUNK 4                    // K chunks of 32 (fp16: 64 B per row)
#define PITCH  80                   // bytes per row per chunk (20 words)
#define PITCHW 20
#define ACH    (TM  * PITCH)        // 10240
#define BCH    (TNJ * PITCH)        // 20480
#define SM_A   0
#define SM_B   (NCHUNK * ACH)       // 40960
#define SM_STG (SM_B + NCHUNK * BCH)// 122880
#define STGSZ  3072
#define SM_TOT (SM_STG + 2 * STGSZ) // 129024

__device__ float      g_sq[BN];
__device__ int        g_lab[BN];
__device__ uint32_t   g_f16[BN * DIM / 2];   // packed half2, natural k order
__device__ float      g_partials[NBLK2];
__device__ long long  g_poscnt[NBLK2];
__device__ unsigned   g_ticket;

__device__ __forceinline__ uint32_t smem_u32(const void* p) {
    uint32_t a;
    asm("{ .reg .u64 t; cvta.to.shared.u64 t, %1; cvt.u32.u64 %0, t; }" : "=r"(a) : "l"(p));
    return a;
}
__device__ __forceinline__ void cp16(uint32_t dst, const void* src) {
    asm volatile("cp.async.cg.shared.global [%0], [%1], 16;" :: "r"(dst), "l"(src));
}
__device__ __forceinline__ void cp_commit() {
    asm volatile("cp.async.commit_group;" ::: "memory");
}
template<int N> __device__ __forceinline__ void cp_wait() {
    asm volatile("cp.async.wait_group %0;" :: "n"(N) : "memory");
}
__device__ __forceinline__ void mma_f16(float c[4], uint32_t a0, uint32_t a1,
                                        uint32_t a2, uint32_t a3,
                                        uint32_t b0, uint32_t b1) {
    asm volatile(
        "mma.sync.aligned.m16n8k16.row.col.f32.f16.f16.f32 "
        "{%0,%1,%2,%3}, {%4,%5,%6,%7}, {%8,%9}, {%0,%1,%2,%3};"
        : "+f"(c[0]), "+f"(c[1]), "+f"(c[2]), "+f"(c[3])
        : "r"(a0), "r"(a1), "r"(a2), "r"(a3), "r"(b0), "r"(b1));
}
__device__ __forceinline__ void decode_tile(int idx, int& i0, int& j0) {
    int bi = 0;
    while (idx >= 32 - (bi >> 1)) { idx -= 32 - (bi >> 1); bi++; }
    i0 = bi * TM;
    j0 = ((bi >> 1) + idx) * TNJ;
}

// ---------------------------------------------------------------------------
// Kernel 0: norms (exact fp32), labels, fp16 packed copy.
// ---------------------------------------------------------------------------
__global__ void prep_kernel(const float* __restrict__ F,
                            const void* __restrict__ labels_raw) {
    if (blockIdx.x == 0 && threadIdx.x == 0) g_ticket = 0;  // reset per replay

    int warp = (blockIdx.x * blockDim.x + threadIdx.x) >> 5;
    int lane = threadIdx.x & 31;
    if (warp >= BN) return;

    const int* w = (const int*)labels_raw;
    int probe = w[2 * lane + 1];
    unsigned is64 = __all_sync(0xffffffffu, probe == 0);

    const float4* row = (const float4*)(F + (size_t)warp * DIM);
    float4 f = row[lane];

    __half2 h0 = __floats2half2_rn(f.x, f.y);
    __half2 h1 = __floats2half2_rn(f.z, f.w);
    uint2 hp = { *(uint32_t*)&h0, *(uint32_t*)&h1 };
    *(uint2*)&g_f16[(size_t)warp * 64 + lane * 2] = hp;

    float s = f.x * f.x + f.y * f.y + f.z * f.z + f.w * f.w;
    #pragma unroll
    for (int off = 16; off; off >>= 1)
        s += __shfl_xor_sync(0xffffffffu, s, off);

    if (lane == 0) {
        g_sq[warp] = s;
        int lab;
        if (is64) lab = (int)((const long long*)labels_raw)[warp];
        else      lab = w[warp];
        g_lab[warp] = lab;
    }
}

// ---------------------------------------------------------------------------
// Issue cp.async for one K=32 chunk of one tile into ring buffer c.
__device__ __forceinline__ void issue_chunk(uint32_t sbase, int i0, int j0,
                                            int c, int t) {
    const char* P = (const char*)g_f16;           // 256 B per feature row
    #pragma unroll
    for (int s = t; s < TM * 4; s += 256) {       // A: 512 16B segs
        int r = s >> 2, q = s & 3;
        cp16(sbase + SM_A + c * ACH + r * PITCH + q * 16,
             P + (size_t)(i0 + r) * 256 + c * 64 + q * 16);
    }
    #pragma unroll
    for (int s = t; s < TNJ * 4; s += 256) {      // B: 1024 16B segs
        int r = s >> 2, q = s & 3;
        cp16(sbase + SM_B + c * BCH + r * PITCH + q * 16,
             P + (size_t)(j0 + r) * 256 + c * 64 + q * 16);
    }
}

// ---------------------------------------------------------------------------
__global__ void __launch_bounds__(256, 1)
tile_kernel() {
    extern __shared__ char smem[];
    uint32_t sbase = smem_u32(smem);

    int t = threadIdx.x;
    int wid = t >> 5, lane = t & 31;
    int gid = lane >> 2, tig = lane & 3;
    int wm = wid & 1, wn = wid >> 1;
    int mbase = wm * 64, nbase = wn * 64;

    __shared__ int s_tick;
    __shared__ float rbuf[8];
    __shared__ int   rcnt[8];

    if (t == 0) s_tick = (int)atomicAdd(&g_ticket, 1u);
    __syncthreads();
    int cur = s_tick;
    if (cur >= NBLK2) return;

    int i0, j0;
    decode_tile(cur, i0, j0);

    // prologue: fill all 4 chunk buffers for the first tile
    #pragma unroll
    for (int c = 0; c < NCHUNK; c++) {
        issue_chunk(sbase, i0, j0, c, t);
        cp_commit();
    }

    int parity = 0;
    for (;;) {
        if (t == 0) s_tick = (int)atomicAdd(&g_ticket, 1u);
        {
            char* stg = smem + SM_STG + parity * STGSZ;
            float* sqI = (float*)stg;
            float* sqJ = (float*)(stg + 512);
            int*   lbI = (int*)  (stg + 1536);
            int*   lbJ = (int*)  (stg + 2048);
            if (t < TM) { sqI[t] = g_sq[i0 + t]; lbI[t] = g_lab[i0 + t]; }
            sqJ[t] = g_sq[j0 + t];
            lbJ[t] = g_lab[j0 + t];
        }
        __syncthreads();
        int nxt = s_tick;
        int ni0 = 0, nj0 = 0;
        bool more = (nxt < NBLK2);
        if (more) decode_tile(nxt, ni0, nj0);

        float acc[4][8][4];
        #pragma unroll
        for (int mf = 0; mf < 4; mf++)
            #pragma unroll
            for (int nf = 0; nf < 8; nf++)
                #pragma unroll
                for (int rr = 0; rr < 4; rr++) acc[mf][nf][rr] = 0.0f;

        // ring over 4 K=32 chunks: compute chunk c, refill with next tile's c
        #pragma unroll
        for (int c = 0; c < NCHUNK; c++) {
            cp_wait<3>();
            __syncthreads();

            const uint32_t* Ac = (const uint32_t*)(smem + SM_A + c * ACH);
            const uint32_t* Bc = (const uint32_t*)(smem + SM_B + c * BCH);

            #pragma unroll
            for (int g = 0; g < 2; g++) {          // 2 k16 steps per chunk
                int kb = g * 8;                    // 8 words per k16 group
                uint32_t a[4][4];
                #pragma unroll
                for (int mf = 0; mf < 4; mf++) {
                    const uint32_t* r0 = Ac + (size_t)(mbase + 16 * mf + gid) * PITCHW + kb;
                    const uint32_t* r1 = Ac + (size_t)(mbase + 16 * mf + gid + 8) * PITCHW + kb;
                    a[mf][0] = r0[tig];
                    a[mf][1] = r1[tig];
                    a[mf][2] = r0[tig + 4];
                    a[mf][3] = r1[tig + 4];
                }
                uint32_t b[8][2];
                #pragma unroll
                for (int nf = 0; nf < 8; nf++) {
                    const uint32_t* rn = Bc + (size_t)(nbase + 8 * nf + gid) * PITCHW + kb;
                    b[nf][0] = rn[tig];
                    b[nf][1] = rn[tig + 4];
                }
                #pragma unroll
                for (int mf = 0; mf < 4; mf++)
                    #pragma unroll
                    for (int nf = 0; nf < 8; nf++)
                        mma_f16(acc[mf][nf], a[mf][0], a[mf][1], a[mf][2], a[mf][3],
                                b[nf][0], b[nf][1]);
            }

            __syncthreads();               // all warps done reading buffer c
            if (more) issue_chunk(sbase, ni0, nj0, c, t);
            cp_commit();                   // possibly-empty group keeps FIFO order
        }

        // ---- fused epilogue: ordered pairs gj > gi, weight x2 ----
        const char* stg = smem + SM_STG + parity * STGSZ;
        const float* sqI = (const float*)stg;
        const float* sqJ = (const float*)(stg + 512);
        const int*   lbI = (const int*)  (stg + 1536);
        const int*   lbJ = (const int*)  (stg + 2048);

        float lsum = 0.0f;
        int   lcnt = 0;
        #pragma unroll
        for (int mf = 0; mf < 4; mf++) {
            #pragma unroll
            for (int rr = 0; rr < 2; rr++) {
                int m  = mbase + 16 * mf + gid + 8 * rr;
                int gi = i0 + m;
                float sqi = sqI[m];
                int   li  = lbI[m];
                #pragma unroll
                for (int nf = 0; nf < 8; nf++) {
                    #pragma unroll
                    for (int cc = 0; cc < 2; cc++) {
                        int n  = nbase + 8 * nf + tig * 2 + cc;
                        int gj = j0 + n;
                        if (gj <= gi) continue;
                        float dot = acc[mf][nf][rr * 2 + cc];
                        float d2 = fmaxf(sqi + sqJ[n] - 2.0f * dot, 0.0f);
                        if (li == lbJ[n]) {
                            lsum += d2;
                            lcnt++;
                        } else if (d2 < MARGIN * MARGIN) {   // ~never (8 sigma)
                            float h = MARGIN - sqrtf(d2);
                            lsum += h * h;
                        }
                    }
                }
            }
        }

        #pragma unroll
        for (int off = 16; off; off >>= 1) {
            lsum += __shfl_xor_sync(0xffffffffu, lsum, off);
            lcnt += __shfl_xor_sync(0xffffffffu, lcnt, off);
        }
        if (lane == 0) { rbuf[wid] = lsum; rcnt[wid] = lcnt; }
        __syncthreads();
        if (t == 0) {
            float s = 0.0f; long long c = 0;
            #pragma unroll
            for (int wd = 0; wd < 8; wd++) { s += rbuf[wd]; c += rcnt[wd]; }
            g_partials[cur] = s * 2.0f;
            g_poscnt[cur]   = c * 2LL;
        }

        if (!more) break;
        cur = nxt; i0 = ni0; j0 = nj0; parity ^= 1;
    }
}

// ---------------------------------------------------------------------------
__global__ void finalize_kernel(float* __restrict__ out) {
    int t = threadIdx.x;
    double s = 0.0; long long c = 0;
    for (int i = t; i < NBLK2; i += 256) {
        s += (double)g_partials[i];
        c += g_poscnt[i];
    }
    __shared__ double    sd[256];
    __shared__ long long sc[256];
    sd[t] = s; sc[t] = c;
    __syncthreads();
    for (int off = 128; off; off >>= 1) {
        if (t < off) { sd[t] += sd[t + off]; sc[t] += sc[t + off]; }
        __syncthreads();
    }
    if (t == 0) {
        double total = sd[0];
        double denom = (double)((long long)BN * (BN - 1));
        out[0] = (float)(sc[0] > 0 ? total / denom : total);
    }
}

// ---------------------------------------------------------------------------
extern "C" void kernel_launch(void* const* d_in, const int* in_sizes, int n_in,
                              void* d_out, int out_size) {
    const float* F      = (const float*)d_in[0];
    const void*  labels = d_in[1];
    float*       out    = (float*)d_out;

    cudaFuncSetAttribute(tile_kernel,
                         cudaFuncAttributeMaxDynamicSharedMemorySize, SM_TOT);

    prep_kernel<<<BN / 8, 256>>>(F, labels);
    tile_kernel<<<NPERS, 256, SM_TOT>>>();
    finalize_kernel<<<1, 256>>>(out);
}

// round 12
// speedup vs baseline: 1.3553x; 1.0179x over previous
#include <cuda_runtime.h>
#include <cuda_fp16.h>
#include <cstdint>

// FeaturesLoss: mma.sync m16n8k16 fp16, persistent 128-thread CTAs with
// 2 CTAs/SM (overlap barriers/epilogue with tensor work), 128x128 tiles
// (64x64/warp), 4-chunk cp.async ring across tiles, ordered-pair (j>i, x2)
// coverage, deterministic reduction.

#define BN    8192
#define DIM   128
#define TM    128
#define NT    (BN / TM)             // 64
#define NBLK  (NT * (NT + 1) / 2)   // 2080 upper-tri tiles
#define MARGIN 2.0f
#define NPERS (152 * 2)             // 2 CTAs per SM

#define NCHUNK 4                    // K chunks of 32 (fp16: 64 B per row)
#define PITCH  80                   // bytes per row per chunk (20 words)
#define PITCHW 20
#define ACH    (TM * PITCH)         // 10240
#define BCH    (TM * PITCH)         // 10240
#define SM_A   0
#define SM_B   (NCHUNK * ACH)       // 40960
#define SM_STG (SM_B + NCHUNK * BCH)// 81920
#define STGSZ  2048                 // sqI/sqJ/lbI/lbJ (512 B each)
#define SM_TOT (SM_STG + 2 * STGSZ) // 86016 B per CTA (x2 CTAs = 172 KB/SM)

__device__ float      g_sq[BN];
__device__ int        g_lab[BN];
__device__ uint32_t   g_f16[BN * DIM / 2];   // packed half2, natural k order
__device__ float      g_partials[NBLK];
__device__ long long  g_poscnt[NBLK];
__device__ unsigned   g_ticket;

__device__ __forceinline__ uint32_t smem_u32(const void* p) {
    uint32_t a;
    asm("{ .reg .u64 t; cvta.to.shared.u64 t, %1; cvt.u32.u64 %0, t; }" : "=r"(a) : "l"(p));
    return a;
}
__device__ __forceinline__ void cp16(uint32_t dst, const void* src) {
    asm volatile("cp.async.cg.shared.global [%0], [%1], 16;" :: "r"(dst), "l"(src));
}
__device__ __forceinline__ void cp_commit() {
    asm volatile("cp.async.commit_group;" ::: "memory");
}
template<int N> __device__ __forceinline__ void cp_wait() {
    asm volatile("cp.async.wait_group %0;" :: "n"(N) : "memory");
}
__device__ __forceinline__ void mma_f16(float c[4], uint32_t a0, uint32_t a1,
                                        uint32_t a2, uint32_t a3,
                                        uint32_t b0, uint32_t b1) {
    asm volatile(
        "mma.sync.aligned.m16n8k16.row.col.f32.f16.f16.f32 "
        "{%0,%1,%2,%3}, {%4,%5,%6,%7}, {%8,%9}, {%0,%1,%2,%3};"
        : "+f"(c[0]), "+f"(c[1]), "+f"(c[2]), "+f"(c[3])
        : "r"(a0), "r"(a1), "r"(a2), "r"(a3), "r"(b0), "r"(b1));
}
__device__ __forceinline__ void decode_tile(int idx, int& i0, int& j0) {
    int bi = 0;
    while (idx >= NT - bi) { idx -= NT - bi; bi++; }
    i0 = bi * TM;
    j0 = (bi + idx) * TM;
}

// ---------------------------------------------------------------------------
// Kernel 0: norms (exact fp32), labels (int64/int32 probe), fp16 packed copy.
// ---------------------------------------------------------------------------
__global__ void prep_kernel(const float* __restrict__ F,
                            const void* __restrict__ labels_raw) {
    if (blockIdx.x == 0 && threadIdx.x == 0) g_ticket = 0;  // reset per replay

    int warp = (blockIdx.x * blockDim.x + threadIdx.x) >> 5;
    int lane = threadIdx.x & 31;
    if (warp >= BN) return;

    const int* w = (const int*)labels_raw;
    int probe = w[2 * lane + 1];
    unsigned is64 = __all_sync(0xffffffffu, probe == 0);

    const float4* row = (const float4*)(F + (size_t)warp * DIM);
    float4 f = row[lane];

    __half2 h0 = __floats2half2_rn(f.x, f.y);
    __half2 h1 = __floats2half2_rn(f.z, f.w);
    uint2 hp = { *(uint32_t*)&h0, *(uint32_t*)&h1 };
    *(uint2*)&g_f16[(size_t)warp * 64 + lane * 2] = hp;

    float s = f.x * f.x + f.y * f.y + f.z * f.z + f.w * f.w;
    #pragma unroll
    for (int off = 16; off; off >>= 1)
        s += __shfl_xor_sync(0xffffffffu, s, off);

    if (lane == 0) {
        g_sq[warp] = s;
        int lab;
        if (is64) lab = (int)((const long long*)labels_raw)[warp];
        else      lab = w[warp];
        g_lab[warp] = lab;
    }
}

// ---------------------------------------------------------------------------
// Issue cp.async for one K=32 chunk of tile (i0,j0) into ring buffer c.
// 128 threads: A = 512 16B segs (4 rounds), B same.
__device__ __forceinline__ void issue_chunk(uint32_t sbase, int i0, int j0,
                                            int c, int t) {
    const char* P = (const char*)g_f16;           // 256 B per feature row
    #pragma unroll
    for (int s = t; s < TM * 4; s += 128) {
        int r = s >> 2, q = s & 3;
        cp16(sbase + SM_A + c * ACH + r * PITCH + q * 16,
             P + (size_t)(i0 + r) * 256 + c * 64 + q * 16);
    }
    #pragma unroll
    for (int s = t; s < TM * 4; s += 128) {
        int r = s >> 2, q = s & 3;
        cp16(sbase + SM_B + c * BCH + r * PITCH + q * 16,
             P + (size_t)(j0 + r) * 256 + c * 64 + q * 16);
    }
}

// ---------------------------------------------------------------------------
__global__ void __launch_bounds__(128, 2)
tile_kernel() {
    extern __shared__ char smem[];
    uint32_t sbase = smem_u32(smem);

    int t = threadIdx.x;
    int wid = t >> 5, lane = t & 31;
    int gid = lane >> 2, tig = lane & 3;
    int wm = wid & 1, wn = wid >> 1;     // 4 warps: 2x2 grid of 64x64 subtiles
    int mbase = wm * 64, nbase = wn * 64;

    __shared__ int s_tick;
    __shared__ float rbuf[4];
    __shared__ int   rcnt[4];

    if (t == 0) s_tick = (int)atomicAdd(&g_ticket, 1u);
    __syncthreads();
    int cur = s_tick;
    if (cur >= NBLK) return;

    int i0, j0;
    decode_tile(cur, i0, j0);

    // prologue: fill all 4 chunk buffers for the first tile
    #pragma unroll
    for (int c = 0; c < NCHUNK; c++) {
        issue_chunk(sbase, i0, j0, c, t);
        cp_commit();
    }

    int parity = 0;
    for (;;) {
        if (t == 0) s_tick = (int)atomicAdd(&g_ticket, 1u);
        {
            char* stg = smem + SM_STG + parity * STGSZ;
            float* sqI = (float*)stg;
            float* sqJ = (float*)(stg + 512);
            int*   lbI = (int*)  (stg + 1024);
            int*   lbJ = (int*)  (stg + 1536);
            sqI[t] = g_sq[i0 + t];  lbI[t] = g_lab[i0 + t];
            sqJ[t] = g_sq[j0 + t];  lbJ[t] = g_lab[j0 + t];
        }
        __syncthreads();
        int nxt = s_tick;
        int ni0 = 0, nj0 = 0;
        bool more = (nxt < NBLK);
        if (more) decode_tile(nxt, ni0, nj0);

        float acc[4][8][4];
        #pragma unroll
        for (int mf = 0; mf < 4; mf++)
            #pragma unroll
            for (int nf = 0; nf < 8; nf++)
                #pragma unroll
                for (int rr = 0; rr < 4; rr++) acc[mf][nf][rr] = 0.0f;

        // ring over 4 K=32 chunks: compute chunk c, refill with next tile's c
        #pragma unroll
        for (int c = 0; c < NCHUNK; c++) {
            cp_wait<3>();
            __syncthreads();

            const uint32_t* Ac = (const uint32_t*)(smem + SM_A + c * ACH);
            const uint32_t* Bc = (const uint32_t*)(smem + SM_B + c * BCH);

            #pragma unroll
            for (int g = 0; g < 2; g++) {          // 2 k16 steps per chunk
                int kb = g * 8;
                uint32_t a[4][4];
                #pragma unroll
                for (int mf = 0; mf < 4; mf++) {
                    const uint32_t* r0 = Ac + (size_t)(mbase + 16 * mf + gid) * PITCHW + kb;
                    const uint32_t* r1 = Ac + (size_t)(mbase + 16 * mf + gid + 8) * PITCHW + kb;
                    a[mf][0] = r0[tig];
                    a[mf][1] = r1[tig];
                    a[mf][2] = r0[tig + 4];
                    a[mf][3] = r1[tig + 4];
                }
                uint32_t b[8][2];
                #pragma unroll
                for (int nf = 0; nf < 8; nf++) {
                    const uint32_t* rn = Bc + (size_t)(nbase + 8 * nf + gid) * PITCHW + kb;
                    b[nf][0] = rn[tig];
                    b[nf][1] = rn[tig + 4];
                }
                #pragma unroll
                for (int mf = 0; mf < 4; mf++)
                    #pragma unroll
                    for (int nf = 0; nf < 8; nf++)
                        mma_f16(acc[mf][nf], a[mf][0], a[mf][1], a[mf][2], a[mf][3],
                                b[nf][0], b[nf][1]);
            }

            __syncthreads();               // all warps done reading buffer c
            if (more) issue_chunk(sbase, ni0, nj0, c, t);
            cp_commit();                   // possibly-empty group keeps FIFO order
        }

        // ---- fused epilogue: ordered pairs gj > gi, weight x2 ----
        const char* stg = smem + SM_STG + parity * STGSZ;
        const float* sqI = (const float*)stg;
        const float* sqJ = (const float*)(stg + 512);
        const int*   lbI = (const int*)  (stg + 1024);
        const int*   lbJ = (const int*)  (stg + 1536);

        float lsum = 0.0f;
        int   lcnt = 0;
        #pragma unroll
        for (int mf = 0; mf < 4; mf++) {
            #pragma unroll
            for (int rr = 0; rr < 2; rr++) {
                int m  = mbase + 16 * mf + gid + 8 * rr;
                int gi = i0 + m;
                float sqi = sqI[m];
                int   li  = lbI[m];
                #pragma unroll
                for (int nf = 0; nf < 8; nf++) {
                    #pragma unroll
                    for (int cc = 0; cc < 2; cc++) {
                        int n  = nbase + 8 * nf + tig * 2 + cc;
                        int gj = j0 + n;
                        if (gj <= gi) continue;
                        float dot = acc[mf][nf][rr * 2 + cc];
                        float d2 = fmaxf(sqi + sqJ[n] - 2.0f * dot, 0.0f);
                        if (li == lbJ[n]) {
                            lsum += d2;
                            lcnt++;
                        } else if (d2 < MARGIN * MARGIN) {   // ~never (8 sigma)
                            float h = MARGIN - sqrtf(d2);
                            lsum += h * h;
                        }
                    }
                }
            }
        }

        #pragma unroll
        for (int off = 16; off; off >>= 1) {
            lsum += __shfl_xor_sync(0xffffffffu, lsum, off);
            lcnt += __shfl_xor_sync(0xffffffffu, lcnt, off);
        }
        if (lane == 0) { rbuf[wid] = lsum; rcnt[wid] = lcnt; }
        __syncthreads();
        if (t == 0) {
            float s = 0.0f; long long c = 0;
            #pragma unroll
            for (int wd = 0; wd < 4; wd++) { s += rbuf[wd]; c += rcnt[wd]; }
            g_partials[cur] = s * 2.0f;
            g_poscnt[cur]   = c * 2LL;
        }

        if (!more) break;
        cur = nxt; i0 = ni0; j0 = nj0; parity ^= 1;
    }
}

// ---------------------------------------------------------------------------
__global__ void finalize_kernel(float* __restrict__ out) {
    int t = threadIdx.x;
    double s = 0.0; long long c = 0;
    for (int i = t; i < NBLK; i += 256) {
        s += (double)g_partials[i];
        c += g_poscnt[i];
    }
    __shared__ double    sd[256];
    __shared__ long long sc[256];
    sd[t] = s; sc[t] = c;
    __syncthreads();
    for (int off = 128; off; off >>= 1) {
        if (t < off) { sd[t] += sd[t + off]; sc[t] += sc[t + off]; }
        __syncthreads();
    }
    if (t == 0) {
        double total = sd[0];
        double denom = (double)((long long)BN * (BN - 1));
        out[0] = (float)(sc[0] > 0 ? total / denom : total);
    }
}

// ---------------------------------------------------------------------------
extern "C" void kernel_launch(void* const* d_in, const int* in_sizes, int n_in,
                              void* d_out, int out_size) {
    const float* F      = (const float*)d_in[0];
    const void*  labels = d_in[1];
    float*       out    = (float*)d_out;

    cudaFuncSetAttribute(tile_kernel,
                         cudaFuncAttributeMaxDynamicSharedMemorySize, SM_TOT);

    prep_kernel<<<BN / 8, 256>>>(F, labels);
    tile_kernel<<<NPERS, 128, SM_TOT>>>();
    finalize_kernel<<<1, 256>>>(out);
}